// round 1
// baseline (speedup 1.0000x reference)
#include <cuda_runtime.h>
#include <cstdint>

// Problem constants
#define DATA_DIM 88
#define HID 16
#define ND 48
#define CD 176          // NN_CHANNELS * DATA_DIM
#define PAD_YH 180      // W_yh row stride (conflict-free for LDS.128 phases)
#define PAD_HL 52       // W_hl row stride

// SMEM float offsets
#define OFF_WYH   0                      // 48*180 = 8640
#define OFF_WHL   8640                   // 88*52  = 4576
#define OFF_WXH   13216                  // 16*48  = 768   (col-major: [h][n])
#define OFF_WWH   13984                  // 768
#define OFF_BSUM  14752                  // 48
#define OFF_BHL   14800                  // 88
#define OFF_CONV  14888                  // 8
#define OFF_YPAD  14896                  // 8 warps * 96
#define OFF_YC    15664                  // 8 warps * 176
#define OFF_HB    17072                  // 8 warps * 48
#define SMEM_FLOATS 17456                // 69824 bytes

__device__ __forceinline__ unsigned long long pk(float lo, float hi) {
    unsigned long long r;
    asm("mov.b64 %0, {%1, %2};" : "=l"(r) : "f"(lo), "f"(hi));
    return r;
}
__device__ __forceinline__ float2 upk(unsigned long long v) {
    float2 r;
    asm("mov.b64 {%0, %1}, %2;" : "=f"(r.x), "=f"(r.y) : "l"(v));
    return r;
}
__device__ __forceinline__ unsigned long long ffma2(unsigned long long a,
                                                    unsigned long long b,
                                                    unsigned long long c) {
    unsigned long long d;
    asm("fma.rn.f32x2 %0, %1, %2, %3;" : "=l"(d) : "l"(a), "l"(b), "l"(c));
    return d;
}

__global__ void __launch_bounds__(256)
model8_kernel(const int* __restrict__ gw, const int* __restrict__ gx,
              const float* __restrict__ gy,
              const float* __restrict__ Wxh, const float* __restrict__ bxh,
              const float* __restrict__ Wwh, const float* __restrict__ bwh,
              const float* __restrict__ Wyh, const float* __restrict__ byh,
              const float* __restrict__ Wconv, const float* __restrict__ bconv,
              const float* __restrict__ Whl, const float* __restrict__ bhl,
              float* __restrict__ out, int tok_total)
{
    extern __shared__ float s[];
    float* sWyh  = s + OFF_WYH;
    float* sWhl  = s + OFF_WHL;
    float* sWxh  = s + OFF_WXH;
    float* sWwh  = s + OFF_WWH;
    float* sBsum = s + OFF_BSUM;
    float* sBhl  = s + OFF_BHL;
    float* sConv = s + OFF_CONV;

    const int tid  = threadIdx.x;
    const int warp = tid >> 5;
    const int lane = tid & 31;

    // ---- stage weights into SMEM (padded / transposed) ----
    for (int i = tid; i < ND * CD; i += blockDim.x) {
        int r = i / CD, c = i % CD;
        sWyh[r * PAD_YH + c] = Wyh[i];
    }
    for (int i = tid; i < DATA_DIM * ND; i += blockDim.x) {
        int r = i / ND, c = i % ND;
        sWhl[r * PAD_HL + c] = Whl[i];
    }
    for (int i = tid; i < ND * HID; i += blockDim.x) {
        int n = i / HID, h = i % HID;
        sWxh[h * ND + n] = Wxh[i];
        sWwh[h * ND + n] = Wwh[i];
    }
    for (int i = tid; i < ND; i += blockDim.x)
        sBsum[i] = bxh[i] + bwh[i] + byh[i];
    for (int i = tid; i < DATA_DIM; i += blockDim.x)
        sBhl[i] = bhl[i];
    if (tid < 6) sConv[tid] = Wconv[tid];
    if (tid < 2) sConv[6 + tid] = bconv[tid];

    float* ypad = s + OFF_YPAD + warp * 96;   // y at [4..91], zero pads at [3],[92]
    float* yc   = s + OFF_YC   + warp * CD;   // conv output, layout c*88+d
    float* hb   = s + OFF_HB   + warp * ND;   // hidden vector

    if (lane == 0) { ypad[3] = 0.f; ypad[92] = 0.f; }
    __syncthreads();

    const float wc00 = sConv[0], wc01 = sConv[1], wc02 = sConv[2];
    const float wc10 = sConv[3], wc11 = sConv[4], wc12 = sConv[5];
    const float bc0  = sConv[6], bc1  = sConv[7];

    const bool has1 = lane < 16;   // second GEMM1 row (n = lane+32 < 48)
    const bool has2 = lane < 24;   // third GEMM2 row (d = lane+64 < 88)

    const float* w0 = sWyh + lane * PAD_YH;
    const float* w1 = sWyh + (lane + 32) * PAD_YH;
    const float* r0 = sWhl + lane * PAD_HL;
    const float* r1 = sWhl + (lane + 32) * PAD_HL;
    const float* r2 = sWhl + (lane + 64) * PAD_HL;

    const int gwarp  = blockIdx.x * (blockDim.x >> 5) + warp;
    const int nwarps = gridDim.x * (blockDim.x >> 5);

    for (int tok = gwarp; tok < tok_total; tok += nwarps) {
        // ---- load y row (22 x float4 = 88 floats) ----
        const float4* yrow = (const float4*)(gy + (size_t)tok * DATA_DIM);
        if (lane < 22) {
            float4 v = yrow[lane];
            *(float4*)(ypad + 4 + lane * 4) = v;
        }
        const int xi = gx[tok];
        const int wi = gw[tok];
        __syncwarp();

        // ---- Conv1d(1->2, k=3, pad=1) + ReLU ----
        #pragma unroll
        for (int r = 0; r < 3; r++) {
            int d = lane + r * 32;
            if (d < DATA_DIM) {
                float a = ypad[3 + d], b = ypad[4 + d], c = ypad[5 + d];
                float v0 = fmaf(wc02, c, fmaf(wc01, b, fmaf(wc00, a, bc0)));
                float v1 = fmaf(wc12, c, fmaf(wc11, b, fmaf(wc10, a, bc1)));
                yc[d]            = fmaxf(v0, 0.f);
                yc[DATA_DIM + d] = fmaxf(v1, 0.f);
            }
        }
        __syncwarp();

        // ---- GEMM1: h[n] = relu(gather + sum_j Wyh[n,j]*yc[j]) ----
        unsigned long long a0a = 0ull, a0b = 0ull, a1a = 0ull, a1b = 0ull;
        #pragma unroll
        for (int j = 0; j < CD; j += 4) {
            float4 yv = *(const float4*)(yc + j);
            unsigned long long y01 = pk(yv.x, yv.y);
            unsigned long long y23 = pk(yv.z, yv.w);
            float4 q0 = *(const float4*)(w0 + j);
            a0a = ffma2(pk(q0.x, q0.y), y01, a0a);
            a0b = ffma2(pk(q0.z, q0.w), y23, a0b);
            if (has1) {
                float4 q1 = *(const float4*)(w1 + j);
                a1a = ffma2(pk(q1.x, q1.y), y01, a1a);
                a1b = ffma2(pk(q1.z, q1.w), y23, a1b);
            }
        }
        {
            float2 u = upk(a0a), v = upk(a0b);
            float g = sBsum[lane] + sWxh[xi * ND + lane] + sWwh[wi * ND + lane];
            hb[lane] = fmaxf(g + (u.x + v.x) + (u.y + v.y), 0.f);
        }
        if (has1) {
            int n1 = lane + 32;
            float2 u = upk(a1a), v = upk(a1b);
            float g = sBsum[n1] + sWxh[xi * ND + n1] + sWwh[wi * ND + n1];
            hb[n1] = fmaxf(g + (u.x + v.x) + (u.y + v.y), 0.f);
        }
        __syncwarp();

        // ---- GEMM2: out[d] = bhl[d] + sum_n h[n]*Whl[d,n] ----
        unsigned long long o0a = 0ull, o0b = 0ull;
        unsigned long long o1a = 0ull, o1b = 0ull;
        unsigned long long o2a = 0ull, o2b = 0ull;
        #pragma unroll
        for (int n = 0; n < ND; n += 4) {
            float4 hv = *(const float4*)(hb + n);
            unsigned long long h01 = pk(hv.x, hv.y);
            unsigned long long h23 = pk(hv.z, hv.w);
            float4 b0 = *(const float4*)(r0 + n);
            o0a = ffma2(pk(b0.x, b0.y), h01, o0a);
            o0b = ffma2(pk(b0.z, b0.w), h23, o0b);
            float4 b1 = *(const float4*)(r1 + n);
            o1a = ffma2(pk(b1.x, b1.y), h01, o1a);
            o1b = ffma2(pk(b1.z, b1.w), h23, o1b);
            if (has2) {
                float4 b2 = *(const float4*)(r2 + n);
                o2a = ffma2(pk(b2.x, b2.y), h01, o2a);
                o2b = ffma2(pk(b2.z, b2.w), h23, o2b);
            }
        }
        float* orow = out + (size_t)tok * DATA_DIM;
        {
            float2 u = upk(o0a), v = upk(o0b);
            orow[lane] = sBhl[lane] + (u.x + v.x) + (u.y + v.y);
        }
        {
            float2 u = upk(o1a), v = upk(o1b);
            orow[lane + 32] = sBhl[lane + 32] + (u.x + v.x) + (u.y + v.y);
        }
        if (has2) {
            float2 u = upk(o2a), v = upk(o2b);
            orow[lane + 64] = sBhl[lane + 64] + (u.x + v.x) + (u.y + v.y);
        }
        __syncwarp();
    }
}

extern "C" void kernel_launch(void* const* d_in, const int* in_sizes, int n_in,
                              void* d_out, int out_size)
{
    const int*   w     = (const int*)d_in[0];
    const int*   x     = (const int*)d_in[1];
    const float* y     = (const float*)d_in[2];
    const float* Wxh   = (const float*)d_in[3];
    const float* bxh   = (const float*)d_in[4];
    const float* Wwh   = (const float*)d_in[5];
    const float* bwh   = (const float*)d_in[6];
    const float* Wyh   = (const float*)d_in[7];
    const float* byh   = (const float*)d_in[8];
    const float* Wconv = (const float*)d_in[9];
    const float* bconv = (const float*)d_in[10];
    const float* Whl   = (const float*)d_in[11];
    const float* bhl   = (const float*)d_in[12];
    float* out = (float*)d_out;

    const int tok_total = in_sizes[2] / DATA_DIM;
    const int smem_bytes = SMEM_FLOATS * sizeof(float);

    cudaFuncSetAttribute(model8_kernel,
                         cudaFuncAttributeMaxDynamicSharedMemorySize, smem_bytes);

    model8_kernel<<<444, 256, smem_bytes>>>(
        w, x, y, Wxh, bxh, Wwh, bwh, Wyh, byh, Wconv, bconv, Whl, bhl,
        out, tok_total);
}

// round 2
// speedup vs baseline: 1.0048x; 1.0048x over previous
#include <cuda_runtime.h>
#include <cstdint>

// Problem constants
#define DATA_DIM 88
#define HID 16
#define ND 48
#define CD 176          // NN_CHANNELS * DATA_DIM
#define PAD_YH 180      // W_yh row stride (conflict-free for LDS.128 phases)
#define PAD_HL 52       // W_hl row stride

// SMEM float offsets
#define OFF_WYH   0                      // 48*180 = 8640
#define OFF_WHL   8640                   // 88*52  = 4576
#define OFF_WXH   13216                  // 16*48  = 768   (col-major: [h][n])
#define OFF_WWH   13984                  // 768
#define OFF_BSUM  14752                  // 48
#define OFF_BHL   14800                  // 88
#define OFF_CONV  14888                  // 8
#define OFF_YPAD  14896                  // 8 warps * 96
#define OFF_YC    15664                  // 8 warps * 176
#define OFF_HB    17072                  // 8 warps * 48
#define SMEM_FLOATS 17456                // 69824 bytes

__device__ __forceinline__ unsigned long long pk(float lo, float hi) {
    unsigned long long r;
    asm("mov.b64 %0, {%1, %2};" : "=l"(r) : "f"(lo), "f"(hi));
    return r;
}
__device__ __forceinline__ float2 upk(unsigned long long v) {
    float2 r;
    asm("mov.b64 {%0, %1}, %2;" : "=f"(r.x), "=f"(r.y) : "l"(v));
    return r;
}
__device__ __forceinline__ unsigned long long ffma2(unsigned long long a,
                                                    unsigned long long b,
                                                    unsigned long long c) {
    unsigned long long d;
    asm("fma.rn.f32x2 %0, %1, %2, %3;" : "=l"(d) : "l"(a), "l"(b), "l"(c));
    return d;
}

__global__ void __launch_bounds__(256)
model8_kernel(const int* __restrict__ gw, const int* __restrict__ gx,
              const float* __restrict__ gy,
              const float* __restrict__ Wxh, const float* __restrict__ bxh,
              const float* __restrict__ Wwh, const float* __restrict__ bwh,
              const float* __restrict__ Wyh, const float* __restrict__ byh,
              const float* __restrict__ Wconv, const float* __restrict__ bconv,
              const float* __restrict__ Whl, const float* __restrict__ bhl,
              float* __restrict__ out, int tok_total)
{
    extern __shared__ float s[];
    float* sWyh  = s + OFF_WYH;
    float* sWhl  = s + OFF_WHL;
    float* sWxh  = s + OFF_WXH;
    float* sWwh  = s + OFF_WWH;
    float* sBsum = s + OFF_BSUM;
    float* sBhl  = s + OFF_BHL;
    float* sConv = s + OFF_CONV;

    const int tid  = threadIdx.x;
    const int warp = tid >> 5;
    const int lane = tid & 31;

    // ---- stage weights into SMEM (padded / transposed) ----
    for (int i = tid; i < ND * CD; i += blockDim.x) {
        int r = i / CD, c = i % CD;
        sWyh[r * PAD_YH + c] = Wyh[i];
    }
    for (int i = tid; i < DATA_DIM * ND; i += blockDim.x) {
        int r = i / ND, c = i % ND;
        sWhl[r * PAD_HL + c] = Whl[i];
    }
    for (int i = tid; i < ND * HID; i += blockDim.x) {
        int n = i / HID, h = i % HID;
        sWxh[h * ND + n] = Wxh[i];
        sWwh[h * ND + n] = Wwh[i];
    }
    for (int i = tid; i < ND; i += blockDim.x)
        sBsum[i] = bxh[i] + bwh[i] + byh[i];
    for (int i = tid; i < DATA_DIM; i += blockDim.x)
        sBhl[i] = bhl[i];
    if (tid < 6) sConv[tid] = Wconv[tid];
    if (tid < 2) sConv[6 + tid] = bconv[tid];

    float* ypad = s + OFF_YPAD + warp * 96;   // y at [4..91], zero pads at [3],[92]
    float* yc   = s + OFF_YC   + warp * CD;   // conv output, layout c*88+d
    float* hb   = s + OFF_HB   + warp * ND;   // hidden vector

    if (lane == 0) { ypad[3] = 0.f; ypad[92] = 0.f; }
    __syncthreads();

    const float wc00 = sConv[0], wc01 = sConv[1], wc02 = sConv[2];
    const float wc10 = sConv[3], wc11 = sConv[4], wc12 = sConv[5];
    const float bc0  = sConv[6], bc1  = sConv[7];

    const bool has1 = lane < 16;   // second GEMM1 row (n = lane+32 < 48)
    const bool has2 = lane < 24;   // third GEMM2 row (d = lane+64 < 88)

    const float* w0 = sWyh + lane * PAD_YH;
    const float* w1 = sWyh + (lane + 32) * PAD_YH;
    const float* r0 = sWhl + lane * PAD_HL;
    const float* r1 = sWhl + (lane + 32) * PAD_HL;
    const float* r2 = sWhl + (lane + 64) * PAD_HL;

    const int gwarp  = blockIdx.x * (blockDim.x >> 5) + warp;
    const int nwarps = gridDim.x * (blockDim.x >> 5);

    for (int tok = gwarp; tok < tok_total; tok += nwarps) {
        // ---- load y row (22 x float4 = 88 floats) ----
        const float4* yrow = (const float4*)(gy + (size_t)tok * DATA_DIM);
        if (lane < 22) {
            float4 v = yrow[lane];
            *(float4*)(ypad + 4 + lane * 4) = v;
        }
        const int xi = gx[tok];
        const int wi = gw[tok];
        __syncwarp();

        // ---- Conv1d(1->2, k=3, pad=1) + ReLU ----
        #pragma unroll
        for (int r = 0; r < 3; r++) {
            int d = lane + r * 32;
            if (d < DATA_DIM) {
                float a = ypad[3 + d], b = ypad[4 + d], c = ypad[5 + d];
                float v0 = fmaf(wc02, c, fmaf(wc01, b, fmaf(wc00, a, bc0)));
                float v1 = fmaf(wc12, c, fmaf(wc11, b, fmaf(wc10, a, bc1)));
                yc[d]            = fmaxf(v0, 0.f);
                yc[DATA_DIM + d] = fmaxf(v1, 0.f);
            }
        }
        __syncwarp();

        // ---- GEMM1: h[n] = relu(gather + sum_j Wyh[n,j]*yc[j]) ----
        unsigned long long a0a = 0ull, a0b = 0ull, a1a = 0ull, a1b = 0ull;
        #pragma unroll
        for (int j = 0; j < CD; j += 4) {
            float4 yv = *(const float4*)(yc + j);
            unsigned long long y01 = pk(yv.x, yv.y);
            unsigned long long y23 = pk(yv.z, yv.w);
            float4 q0 = *(const float4*)(w0 + j);
            a0a = ffma2(pk(q0.x, q0.y), y01, a0a);
            a0b = ffma2(pk(q0.z, q0.w), y23, a0b);
            if (has1) {
                float4 q1 = *(const float4*)(w1 + j);
                a1a = ffma2(pk(q1.x, q1.y), y01, a1a);
                a1b = ffma2(pk(q1.z, q1.w), y23, a1b);
            }
        }
        {
            float2 u = upk(a0a), v = upk(a0b);
            float g = sBsum[lane] + sWxh[xi * ND + lane] + sWwh[wi * ND + lane];
            hb[lane] = fmaxf(g + (u.x + v.x) + (u.y + v.y), 0.f);
        }
        if (has1) {
            int n1 = lane + 32;
            float2 u = upk(a1a), v = upk(a1b);
            float g = sBsum[n1] + sWxh[xi * ND + n1] + sWwh[wi * ND + n1];
            hb[n1] = fmaxf(g + (u.x + v.x) + (u.y + v.y), 0.f);
        }
        __syncwarp();

        // ---- GEMM2: out[d] = bhl[d] + sum_n h[n]*Whl[d,n] ----
        unsigned long long o0a = 0ull, o0b = 0ull;
        unsigned long long o1a = 0ull, o1b = 0ull;
        unsigned long long o2a = 0ull, o2b = 0ull;
        #pragma unroll
        for (int n = 0; n < ND; n += 4) {
            float4 hv = *(const float4*)(hb + n);
            unsigned long long h01 = pk(hv.x, hv.y);
            unsigned long long h23 = pk(hv.z, hv.w);
            float4 b0 = *(const float4*)(r0 + n);
            o0a = ffma2(pk(b0.x, b0.y), h01, o0a);
            o0b = ffma2(pk(b0.z, b0.w), h23, o0b);
            float4 b1 = *(const float4*)(r1 + n);
            o1a = ffma2(pk(b1.x, b1.y), h01, o1a);
            o1b = ffma2(pk(b1.z, b1.w), h23, o1b);
            if (has2) {
                float4 b2 = *(const float4*)(r2 + n);
                o2a = ffma2(pk(b2.x, b2.y), h01, o2a);
                o2b = ffma2(pk(b2.z, b2.w), h23, o2b);
            }
        }
        float* orow = out + (size_t)tok * DATA_DIM;
        {
            float2 u = upk(o0a), v = upk(o0b);
            orow[lane] = sBhl[lane] + (u.x + v.x) + (u.y + v.y);
        }
        {
            float2 u = upk(o1a), v = upk(o1b);
            orow[lane + 32] = sBhl[lane + 32] + (u.x + v.x) + (u.y + v.y);
        }
        if (has2) {
            float2 u = upk(o2a), v = upk(o2b);
            orow[lane + 64] = sBhl[lane + 64] + (u.x + v.x) + (u.y + v.y);
        }
        __syncwarp();
    }
}

extern "C" void kernel_launch(void* const* d_in, const int* in_sizes, int n_in,
                              void* d_out, int out_size)
{
    const int*   w     = (const int*)d_in[0];
    const int*   x     = (const int*)d_in[1];
    const float* y     = (const float*)d_in[2];
    const float* Wxh   = (const float*)d_in[3];
    const float* bxh   = (const float*)d_in[4];
    const float* Wwh   = (const float*)d_in[5];
    const float* bwh   = (const float*)d_in[6];
    const float* Wyh   = (const float*)d_in[7];
    const float* byh   = (const float*)d_in[8];
    const float* Wconv = (const float*)d_in[9];
    const float* bconv = (const float*)d_in[10];
    const float* Whl   = (const float*)d_in[11];
    const float* bhl   = (const float*)d_in[12];
    float* out = (float*)d_out;

    const int tok_total = in_sizes[2] / DATA_DIM;
    const int smem_bytes = SMEM_FLOATS * sizeof(float);

    cudaFuncSetAttribute(model8_kernel,
                         cudaFuncAttributeMaxDynamicSharedMemorySize, smem_bytes);

    model8_kernel<<<444, 256, smem_bytes>>>(
        w, x, y, Wxh, bxh, Wwh, bwh, Wyh, byh, Wconv, bconv, Whl, bhl,
        out, tok_total);
}

// round 3
// speedup vs baseline: 2.0489x; 2.0391x over previous
#include <cuda_runtime.h>
#include <cstdint>

// Problem constants
#define DATA_DIM 88
#define HID 16
#define ND 48
#define CD 176          // NN_CHANNELS * DATA_DIM
#define PAD_YH 180      // W_yh row stride (conflict-free LDS.128 phases: 45L mod 8 bijective)
#define PAD_HL 52       // W_hl row stride (13L mod 8 bijective)
#define TB 4            // tokens per warp iteration

// SMEM float offsets
#define OFF_WYH   0                      // 48*180 = 8640
#define OFF_WHL   8640                   // 88*52  = 4576
#define OFF_WXH   13216                  // 16*48  = 768   (col-major: [h][n])
#define OFF_WWH   13984                  // 768
#define OFF_BSUM  14752                  // 48
#define OFF_BHL   14800                  // 88
#define OFF_CONV  14888                  // 8
#define OFF_YPAD  14896                  // 8 warps * 4 tok * 96  = 3072
#define OFF_YC    17968                  // 8 warps * 4 tok * 176 = 5632
#define OFF_HB    23600                  // 8 warps * 4 tok * 48  = 1536
#define SMEM_FLOATS 25136                // 100544 bytes

__device__ __forceinline__ unsigned long long pk(float lo, float hi) {
    unsigned long long r;
    asm("mov.b64 %0, {%1, %2};" : "=l"(r) : "f"(lo), "f"(hi));
    return r;
}
__device__ __forceinline__ float2 upk(unsigned long long v) {
    float2 r;
    asm("mov.b64 {%0, %1}, %2;" : "=f"(r.x), "=f"(r.y) : "l"(v));
    return r;
}
__device__ __forceinline__ unsigned long long ffma2(unsigned long long a,
                                                    unsigned long long b,
                                                    unsigned long long c) {
    unsigned long long d;
    asm("fma.rn.f32x2 %0, %1, %2, %3;" : "=l"(d) : "l"(a), "l"(b), "l"(c));
    return d;
}

__global__ void __launch_bounds__(256, 2)
model8_kernel(const int* __restrict__ gw, const int* __restrict__ gx,
              const float* __restrict__ gy,
              const float* __restrict__ Wxh, const float* __restrict__ bxh,
              const float* __restrict__ Wwh, const float* __restrict__ bwh,
              const float* __restrict__ Wyh, const float* __restrict__ byh,
              const float* __restrict__ Wconv, const float* __restrict__ bconv,
              const float* __restrict__ Whl, const float* __restrict__ bhl,
              float* __restrict__ out, int tok_total)
{
    extern __shared__ float s[];
    float* sWyh  = s + OFF_WYH;
    float* sWhl  = s + OFF_WHL;
    float* sWxh  = s + OFF_WXH;
    float* sWwh  = s + OFF_WWH;
    float* sBsum = s + OFF_BSUM;
    float* sBhl  = s + OFF_BHL;
    float* sConv = s + OFF_CONV;

    const int tid  = threadIdx.x;
    const int warp = tid >> 5;
    const int lane = tid & 31;

    // ---- stage weights into SMEM (padded / transposed) ----
    for (int i = tid; i < ND * CD; i += blockDim.x) {
        int r = i / CD, c = i % CD;
        sWyh[r * PAD_YH + c] = Wyh[i];
    }
    for (int i = tid; i < DATA_DIM * ND; i += blockDim.x) {
        int r = i / ND, c = i % ND;
        sWhl[r * PAD_HL + c] = Whl[i];
    }
    for (int i = tid; i < ND * HID; i += blockDim.x) {
        int n = i / HID, h = i % HID;
        sWxh[h * ND + n] = Wxh[i];
        sWwh[h * ND + n] = Wwh[i];
    }
    for (int i = tid; i < ND; i += blockDim.x)
        sBsum[i] = bxh[i] + bwh[i] + byh[i];
    for (int i = tid; i < DATA_DIM; i += blockDim.x)
        sBhl[i] = bhl[i];
    if (tid < 6) sConv[tid] = Wconv[tid];
    if (tid < 2) sConv[6 + tid] = bconv[tid];

    float* ypad = s + OFF_YPAD + warp * (TB * 96);   // per tok: y at [4..91], zeros at [3],[92]
    float* yc   = s + OFF_YC   + warp * (TB * CD);   // per tok: conv output, c*88+d
    float* hb   = s + OFF_HB   + warp * (TB * ND);   // per tok: hidden vector

    if (lane < TB) { ypad[lane * 96 + 3] = 0.f; ypad[lane * 96 + 92] = 0.f; }
    __syncthreads();

    const float wc00 = sConv[0], wc01 = sConv[1], wc02 = sConv[2];
    const float wc10 = sConv[3], wc11 = sConv[4], wc12 = sConv[5];
    const float bc0  = sConv[6], bc1  = sConv[7];

    const bool has1 = lane < 16;   // second GEMM1 row (n = lane+32 < 48)
    const bool has2 = lane < 24;   // third GEMM2 row (d = lane+64 < 88)

    const float* w0 = sWyh + lane * PAD_YH;
    const float* w1 = sWyh + (lane + 32) * PAD_YH;
    const float* r0 = sWhl + lane * PAD_HL;
    const float* r1 = sWhl + (lane + 32) * PAD_HL;
    const float* r2 = sWhl + (lane + 64) * PAD_HL;

    const int gwarp  = blockIdx.x * (blockDim.x >> 5) + warp;
    const int nwarps = gridDim.x * (blockDim.x >> 5);
    const int niter  = tok_total / TB;

    for (int it = gwarp; it < niter; it += nwarps) {
        const int tok0 = it * TB;

        // ---- load y rows + indices for TB tokens ----
        int xi[TB], wi[TB];
        #pragma unroll
        for (int t = 0; t < TB; t++) {
            const float4* yrow = (const float4*)(gy + (size_t)(tok0 + t) * DATA_DIM);
            if (lane < 22)
                *(float4*)(ypad + t * 96 + 4 + lane * 4) = yrow[lane];
            xi[t] = gx[tok0 + t];
            wi[t] = gw[tok0 + t];
        }
        __syncwarp();

        // ---- Conv1d(1->2, k=3, pad=1) + ReLU for TB tokens ----
        #pragma unroll
        for (int t = 0; t < TB; t++) {
            const float* yp = ypad + t * 96;
            float* yct = yc + t * CD;
            #pragma unroll
            for (int r = 0; r < 3; r++) {
                int d = lane + r * 32;
                if (d < DATA_DIM) {
                    float a = yp[3 + d], b = yp[4 + d], c = yp[5 + d];
                    float v0 = fmaf(wc02, c, fmaf(wc01, b, fmaf(wc00, a, bc0)));
                    float v1 = fmaf(wc12, c, fmaf(wc11, b, fmaf(wc10, a, bc1)));
                    yct[d]            = fmaxf(v0, 0.f);
                    yct[DATA_DIM + d] = fmaxf(v1, 0.f);
                }
            }
        }
        __syncwarp();

        // ---- GEMM1: weights loaded once per TB tokens ----
        unsigned long long A[TB][4];
        #pragma unroll
        for (int t = 0; t < TB; t++)
            A[t][0] = A[t][1] = A[t][2] = A[t][3] = 0ull;

        #pragma unroll 2
        for (int j = 0; j < CD; j += 4) {
            float4 q0 = *(const float4*)(w0 + j);
            unsigned long long u01 = pk(q0.x, q0.y), u23 = pk(q0.z, q0.w);
            unsigned long long v01 = 0ull, v23 = 0ull;
            if (has1) {
                float4 q1 = *(const float4*)(w1 + j);
                v01 = pk(q1.x, q1.y); v23 = pk(q1.z, q1.w);
            }
            #pragma unroll
            for (int t = 0; t < TB; t++) {
                float4 yv = *(const float4*)(yc + t * CD + j);
                unsigned long long y01 = pk(yv.x, yv.y), y23 = pk(yv.z, yv.w);
                A[t][0] = ffma2(u01, y01, A[t][0]);
                A[t][1] = ffma2(u23, y23, A[t][1]);
                A[t][2] = ffma2(v01, y01, A[t][2]);
                A[t][3] = ffma2(v23, y23, A[t][3]);
            }
        }

        #pragma unroll
        for (int t = 0; t < TB; t++) {
            {
                float2 u = upk(A[t][0]), v = upk(A[t][1]);
                float g = sBsum[lane] + sWxh[xi[t] * ND + lane] + sWwh[wi[t] * ND + lane];
                hb[t * ND + lane] = fmaxf(g + (u.x + v.x) + (u.y + v.y), 0.f);
            }
            if (has1) {
                int n1 = lane + 32;
                float2 u = upk(A[t][2]), v = upk(A[t][3]);
                float g = sBsum[n1] + sWxh[xi[t] * ND + n1] + sWwh[wi[t] * ND + n1];
                hb[t * ND + n1] = fmaxf(g + (u.x + v.x) + (u.y + v.y), 0.f);
            }
        }
        __syncwarp();

        // ---- GEMM2: 3 rows (lane, lane+32, lane+64) x TB tokens ----
        unsigned long long O[TB][6];
        #pragma unroll
        for (int t = 0; t < TB; t++)
            O[t][0] = O[t][1] = O[t][2] = O[t][3] = O[t][4] = O[t][5] = 0ull;

        #pragma unroll 2
        for (int n = 0; n < ND; n += 4) {
            float4 b0 = *(const float4*)(r0 + n);
            unsigned long long p01 = pk(b0.x, b0.y), p23 = pk(b0.z, b0.w);
            float4 b1 = *(const float4*)(r1 + n);
            unsigned long long q01 = pk(b1.x, b1.y), q23 = pk(b1.z, b1.w);
            unsigned long long s01 = 0ull, s23 = 0ull;
            if (has2) {
                float4 b2 = *(const float4*)(r2 + n);
                s01 = pk(b2.x, b2.y); s23 = pk(b2.z, b2.w);
            }
            #pragma unroll
            for (int t = 0; t < TB; t++) {
                float4 hv = *(const float4*)(hb + t * ND + n);
                unsigned long long h01 = pk(hv.x, hv.y), h23 = pk(hv.z, hv.w);
                O[t][0] = ffma2(p01, h01, O[t][0]);
                O[t][1] = ffma2(p23, h23, O[t][1]);
                O[t][2] = ffma2(q01, h01, O[t][2]);
                O[t][3] = ffma2(q23, h23, O[t][3]);
                O[t][4] = ffma2(s01, h01, O[t][4]);
                O[t][5] = ffma2(s23, h23, O[t][5]);
            }
        }

        #pragma unroll
        for (int t = 0; t < TB; t++) {
            float* orow = out + (size_t)(tok0 + t) * DATA_DIM;
            {
                float2 u = upk(O[t][0]), v = upk(O[t][1]);
                orow[lane] = sBhl[lane] + (u.x + v.x) + (u.y + v.y);
            }
            {
                float2 u = upk(O[t][2]), v = upk(O[t][3]);
                orow[lane + 32] = sBhl[lane + 32] + (u.x + v.x) + (u.y + v.y);
            }
            if (has2) {
                float2 u = upk(O[t][4]), v = upk(O[t][5]);
                orow[lane + 64] = sBhl[lane + 64] + (u.x + v.x) + (u.y + v.y);
            }
        }
        __syncwarp();
    }
}

extern "C" void kernel_launch(void* const* d_in, const int* in_sizes, int n_in,
                              void* d_out, int out_size)
{
    const int*   w     = (const int*)d_in[0];
    const int*   x     = (const int*)d_in[1];
    const float* y     = (const float*)d_in[2];
    const float* Wxh   = (const float*)d_in[3];
    const float* bxh   = (const float*)d_in[4];
    const float* Wwh   = (const float*)d_in[5];
    const float* bwh   = (const float*)d_in[6];
    const float* Wyh   = (const float*)d_in[7];
    const float* byh   = (const float*)d_in[8];
    const float* Wconv = (const float*)d_in[9];
    const float* bconv = (const float*)d_in[10];
    const float* Whl   = (const float*)d_in[11];
    const float* bhl   = (const float*)d_in[12];
    float* out = (float*)d_out;

    const int tok_total = in_sizes[2] / DATA_DIM;
    const int smem_bytes = SMEM_FLOATS * sizeof(float);

    cudaFuncSetAttribute(model8_kernel,
                         cudaFuncAttributeMaxDynamicSharedMemorySize, smem_bytes);

    model8_kernel<<<296, 256, smem_bytes>>>(
        w, x, y, Wxh, bxh, Wwh, bwh, Wyh, byh, Wconv, bconv, Whl, bhl,
        out, tok_total);
}

// round 6
// speedup vs baseline: 2.9636x; 1.4464x over previous
#include <cuda_runtime.h>
#include <cuda_bf16.h>
#include <cstdint>

#define DATA_DIM 88
#define HID 16
#define ND 48
#define CD 176
#define TOK_TILE 128
#define THREADS 256

// strides in u32 (pair) units; all ≡ 28 (mod 32) => conflict-free fragment loads
#define SA1 92     // A1: 88 data pairs
#define SB1 92     // B1: 88 data pairs
#define SH  28     // H:  24 data pairs
#define SB2 28     // B2: 24 data pairs

// SMEM byte offsets
#define OFF_A1HI 0
#define OFF_A1LO 47104
#define OFF_B1HI 94208
#define OFF_B1LO 111872
#define OFF_HHI  129536
#define OFF_HLO  143872
#define OFF_B2HI 158208
#define OFF_B2LO 168064
#define OFF_WXH  177920
#define OFF_WWH  180992
#define OFF_BSUM 184064
#define OFF_BHL  184256
#define OFF_XI   184608
#define OFF_WI   185120
#define SMEM_TOTAL 185632

__device__ __forceinline__ uint32_t cvt_bf2(float lo, float hi) {
    uint32_t r;
    asm("cvt.rn.bf16x2.f32 %0, %1, %2;" : "=r"(r) : "f"(hi), "f"(lo));
    return r;
}
__device__ __forceinline__ float bfr(float v) {
    return __bfloat162float(__float2bfloat16_rn(v));
}
__device__ __forceinline__ void mma_bf16(float* c,
                                         uint32_t a0, uint32_t a1, uint32_t a2, uint32_t a3,
                                         uint32_t b0, uint32_t b1) {
    asm volatile(
        "mma.sync.aligned.m16n8k16.row.col.f32.bf16.bf16.f32 "
        "{%0,%1,%2,%3}, {%4,%5,%6,%7}, {%8,%9}, {%0,%1,%2,%3};\n"
        : "+f"(c[0]), "+f"(c[1]), "+f"(c[2]), "+f"(c[3])
        : "r"(a0), "r"(a1), "r"(a2), "r"(a3), "r"(b0), "r"(b1));
}

// conv output for tone d (d is a compile-time constant after unroll)
#define CONV(d) fmaxf(fmaf(wc2, ((d) == 87 ? 0.f : yr[(d) + 1]), \
                      fmaf(wc1, yr[d], fmaf(wc0, ((d) == 0 ? 0.f : yr[(d) - 1]), bc))), 0.f)

__global__ void __launch_bounds__(THREADS, 1)
model8_mma(const int* __restrict__ gw, const int* __restrict__ gx,
           const float* __restrict__ gy,
           const float* __restrict__ Wxh, const float* __restrict__ bxh,
           const float* __restrict__ Wwh, const float* __restrict__ bwh,
           const float* __restrict__ Wyh, const float* __restrict__ byh,
           const float* __restrict__ Wconv, const float* __restrict__ bconv,
           const float* __restrict__ Whl, const float* __restrict__ bhl,
           float* __restrict__ out)
{
    extern __shared__ char smem[];
    uint32_t* A1hi = (uint32_t*)(smem + OFF_A1HI);
    uint32_t* A1lo = (uint32_t*)(smem + OFF_A1LO);
    uint32_t* Hhi  = (uint32_t*)(smem + OFF_HHI);
    uint32_t* Hlo  = (uint32_t*)(smem + OFF_HLO);
    float*    sWxh = (float*)(smem + OFF_WXH);
    float*    sWwh = (float*)(smem + OFF_WWH);
    float*    sBsum= (float*)(smem + OFF_BSUM);
    float*    sBhl = (float*)(smem + OFF_BHL);
    int*      sXI  = (int*)(smem + OFF_XI);
    int*      sWI  = (int*)(smem + OFF_WI);

    const int tid  = threadIdx.x;
    const int tile = blockIdx.x;

    // ---- per-thread conv assignment: token = tid/2, channel = tid&1 ----
    const int token = tid >> 1;
    const int ch    = tid & 1;

    // load y row into registers (22 x LDG.128)
    float yr[DATA_DIM];
    {
        const float4* yrow = (const float4*)(gy + ((size_t)tile * TOK_TILE + token) * DATA_DIM);
        #pragma unroll
        for (int q = 0; q < 22; q++) {
            float4 v = yrow[q];
            yr[4*q] = v.x; yr[4*q+1] = v.y; yr[4*q+2] = v.z; yr[4*q+3] = v.w;
        }
    }
    const float wc0 = __ldg(&Wconv[ch * 3 + 0]);
    const float wc1 = __ldg(&Wconv[ch * 3 + 1]);
    const float wc2 = __ldg(&Wconv[ch * 3 + 2]);
    const float bc  = __ldg(&bconv[ch]);

    // ---- stage weights (bf16 hi/lo split), gathers, biases, indices ----
    for (int i = tid; i < ND * CD; i += THREADS) {
        int n = i / CD, k = i % CD;
        float v = Wyh[i];
        float h = bfr(v);
        uint32_t bo = (uint32_t)(n * SA1 + (k >> 1)) * 4u + (uint32_t)(k & 1) * 2u;
        *(__nv_bfloat16*)(smem + OFF_B1HI + bo) = __float2bfloat16_rn(v);
        *(__nv_bfloat16*)(smem + OFF_B1LO + bo) = __float2bfloat16_rn(v - h);
    }
    for (int i = tid; i < DATA_DIM * ND; i += THREADS) {
        int d = i / ND, k = i % ND;
        float v = Whl[i];
        float h = bfr(v);
        uint32_t bo = (uint32_t)(d * SB2 + (k >> 1)) * 4u + (uint32_t)(k & 1) * 2u;
        *(__nv_bfloat16*)(smem + OFF_B2HI + bo) = __float2bfloat16_rn(v);
        *(__nv_bfloat16*)(smem + OFF_B2LO + bo) = __float2bfloat16_rn(v - h);
    }
    for (int i = tid; i < ND * HID; i += THREADS) {
        int n = i / HID, h = i % HID;
        sWxh[h * ND + n] = Wxh[i];
        sWwh[h * ND + n] = Wwh[i];
    }
    for (int i = tid; i < ND; i += THREADS) sBsum[i] = bxh[i] + bwh[i] + byh[i];
    for (int i = tid; i < DATA_DIM; i += THREADS) sBhl[i] = bhl[i];
    for (int i = tid; i < TOK_TILE; i += THREADS) {
        sXI[i] = gx[(size_t)tile * TOK_TILE + i];
        sWI[i] = gw[(size_t)tile * TOK_TILE + i];
    }
    __syncthreads();   // the only block barrier

    // ---- conv + bf16 split -> A1 (each warp writes exactly its own 16 tokens) ----
    {
        uint32_t base = (uint32_t)token * SA1 + (uint32_t)ch * 44u;  // u32 index, 16B-aligned
        uint4* dh = (uint4*)(A1hi + base);
        uint4* dl = (uint4*)(A1lo + base);
        #pragma unroll
        for (int q = 0; q < 11; q++) {
            float c0 = CONV(8*q+0), c1 = CONV(8*q+1), c2 = CONV(8*q+2), c3 = CONV(8*q+3);
            float c4 = CONV(8*q+4), c5 = CONV(8*q+5), c6 = CONV(8*q+6), c7 = CONV(8*q+7);
            uint4 H4, L4;
            H4.x = cvt_bf2(c0, c1); H4.y = cvt_bf2(c2, c3);
            H4.z = cvt_bf2(c4, c5); H4.w = cvt_bf2(c6, c7);
            L4.x = cvt_bf2(c0 - bfr(c0), c1 - bfr(c1));
            L4.y = cvt_bf2(c2 - bfr(c2), c3 - bfr(c3));
            L4.z = cvt_bf2(c4 - bfr(c4), c5 - bfr(c5));
            L4.w = cvt_bf2(c6 - bfr(c6), c7 - bfr(c7));
            dh[q] = H4;
            dl[q] = L4;
        }
    }
    __syncwarp();

    const int w    = tid >> 5;
    const int lane = tid & 31;
    const int g    = lane >> 2;
    const int tg   = lane & 3;

    // ---- GEMM1: [128x176] x [176x48]^T, split-bf16 3 passes ----
    float acc[6][4];
    #pragma unroll
    for (int j = 0; j < 6; j++)
        acc[j][0] = acc[j][1] = acc[j][2] = acc[j][3] = 0.f;

    const int arow1 = (16 * w + g) * SA1;
    #pragma unroll 1
    for (int pass = 0; pass < 3; pass++) {
        const uint32_t* Ab = (pass == 2) ? A1lo : A1hi;
        const uint32_t* Bb = (pass == 1) ? (const uint32_t*)(smem + OFF_B1LO)
                                         : (const uint32_t*)(smem + OFF_B1HI);
        #pragma unroll
        for (int ks = 0; ks < 11; ks++) {
            int ai = arow1 + tg + 8 * ks;
            uint32_t a0 = Ab[ai],            a1 = Ab[ai + 8 * SA1];
            uint32_t a2 = Ab[ai + 4],        a3 = Ab[ai + 8 * SA1 + 4];
            #pragma unroll
            for (int j = 0; j < 6; j++) {
                int bi = (8 * j + g) * SB1 + tg + 8 * ks;
                mma_bf16(acc[j], a0, a1, a2, a3, Bb[bi], Bb[bi + 4]);
            }
        }
    }

    // ---- epilogue 1: + gathers + bias, relu, split -> H (intra-warp) ----
    {
        const int tok0 = 16 * w + g, tok1 = tok0 + 8;
        const int xi0 = sXI[tok0], wi0 = sWI[tok0];
        const int xi1 = sXI[tok1], wi1 = sWI[tok1];
        #pragma unroll
        for (int j = 0; j < 6; j++) {
            int n0 = 8 * j + 2 * tg;
            float bs0 = sBsum[n0],               bs1 = sBsum[n0 + 1];
            float h0 = fmaxf(acc[j][0] + bs0 + sWxh[xi0 * ND + n0]     + sWwh[wi0 * ND + n0],     0.f);
            float h1 = fmaxf(acc[j][1] + bs1 + sWxh[xi0 * ND + n0 + 1] + sWwh[wi0 * ND + n0 + 1], 0.f);
            float h2 = fmaxf(acc[j][2] + bs0 + sWxh[xi1 * ND + n0]     + sWwh[wi1 * ND + n0],     0.f);
            float h3 = fmaxf(acc[j][3] + bs1 + sWxh[xi1 * ND + n0 + 1] + sWwh[wi1 * ND + n0 + 1], 0.f);
            int i0 = tok0 * SH + 4 * j + tg;
            int i1 = tok1 * SH + 4 * j + tg;
            Hhi[i0] = cvt_bf2(h0, h1);
            Hlo[i0] = cvt_bf2(h0 - bfr(h0), h1 - bfr(h1));
            Hhi[i1] = cvt_bf2(h2, h3);
            Hlo[i1] = cvt_bf2(h2 - bfr(h2), h3 - bfr(h3));
        }
    }
    __syncwarp();

    // ---- GEMM2: [128x48] x [48x88]^T, split-bf16 3 passes ----
    float acc2[11][4];
    #pragma unroll
    for (int j = 0; j < 11; j++)
        acc2[j][0] = acc2[j][1] = acc2[j][2] = acc2[j][3] = 0.f;

    const int arow2 = (16 * w + g) * SH;
    #pragma unroll 1
    for (int pass = 0; pass < 3; pass++) {
        const uint32_t* Ab = (pass == 2) ? Hlo : Hhi;
        const uint32_t* Bb = (pass == 1) ? (const uint32_t*)(smem + OFF_B2LO)
                                         : (const uint32_t*)(smem + OFF_B2HI);
        #pragma unroll
        for (int ks = 0; ks < 3; ks++) {
            int ai = arow2 + tg + 8 * ks;
            uint32_t a0 = Ab[ai],     a1 = Ab[ai + 8 * SH];
            uint32_t a2 = Ab[ai + 4], a3 = Ab[ai + 8 * SH + 4];
            #pragma unroll
            for (int j = 0; j < 11; j++) {
                int bi = (8 * j + g) * SB2 + tg + 8 * ks;
                mma_bf16(acc2[j], a0, a1, a2, a3, Bb[bi], Bb[bi + 4]);
            }
        }
    }

    // ---- epilogue 2: + bias -> global (STG.64) ----
    {
        const int tok0 = 16 * w + g;
        float* ob0 = out + ((size_t)tile * TOK_TILE + tok0) * DATA_DIM;
        float* ob1 = ob0 + 8 * DATA_DIM;
        #pragma unroll
        for (int j = 0; j < 11; j++) {
            int n0 = 8 * j + 2 * tg;
            float b0 = sBhl[n0], b1 = sBhl[n0 + 1];
            float2 v0, v1;
            v0.x = acc2[j][0] + b0; v0.y = acc2[j][1] + b1;
            v1.x = acc2[j][2] + b0; v1.y = acc2[j][3] + b1;
            *(float2*)(ob0 + n0) = v0;
            *(float2*)(ob1 + n0) = v1;
        }
    }
}

extern "C" void kernel_launch(void* const* d_in, const int* in_sizes, int n_in,
                              void* d_out, int out_size)
{
    const int*   w     = (const int*)d_in[0];
    const int*   x     = (const int*)d_in[1];
    const float* y     = (const float*)d_in[2];
    const float* Wxh   = (const float*)d_in[3];
    const float* bxh   = (const float*)d_in[4];
    const float* Wwh   = (const float*)d_in[5];
    const float* bwh   = (const float*)d_in[6];
    const float* Wyh   = (const float*)d_in[7];
    const float* byh   = (const float*)d_in[8];
    const float* Wconv = (const float*)d_in[9];
    const float* bconv = (const float*)d_in[10];
    const float* Whl   = (const float*)d_in[11];
    const float* bhl   = (const float*)d_in[12];
    float* out = (float*)d_out;

    const int tok_total = in_sizes[2] / DATA_DIM;
    const int ntiles = tok_total / TOK_TILE;

    cudaFuncSetAttribute(model8_mma,
                         cudaFuncAttributeMaxDynamicSharedMemorySize, SMEM_TOTAL);

    model8_mma<<<ntiles, THREADS, SMEM_TOTAL>>>(
        w, x, y, Wxh, bxh, Wwh, bwh, Wyh, byh, Wconv, bconv, Whl, bhl, out);
}